// round 13
// baseline (speedup 1.0000x reference)
#include <cuda_runtime.h>
#include <cuda_bf16.h>
#include <cstdint>

#define Bsz 4
#define Hh  16
#define Tt  1024
#define Ff  128
#define BH  64

static const float SCALING = 0.08838834764831845f; // 128^-0.5

__device__ float g_q   [(long)BH * Tt * Ff];
__device__ float g_k   [(long)BH * Tt * Ff];
__device__ float g_v   [(long)BH * Tt * Ff];
__device__ float g_aw  [(long)BH * Tt * Tt];
__device__ float g_attn[(long)Bsz * 32 * Tt * Ff];
__device__ float g_pf  [(long)BH * Ff * Ff];
__device__ float g_pfp [(long)4 * BH * Ff * Ff]; // split-K partials

__device__ __forceinline__ float to_tf32(float x) {
    uint32_t u;
    asm("cvt.rna.tf32.f32 %0, %1;" : "=r"(u) : "f"(x));
    return __uint_as_float(u);
}
__device__ __forceinline__ void mma_tf32(float* d, float a0, float a1,
                                         float a2, float a3, float b0, float b1)
{
    asm volatile(
        "mma.sync.aligned.m16n8k8.row.col.f32.tf32.tf32.f32 "
        "{%0,%1,%2,%3}, {%4,%5,%6,%7}, {%8,%9}, {%0,%1,%2,%3};\n"
        : "+f"(d[0]), "+f"(d[1]), "+f"(d[2]), "+f"(d[3])
        : "r"(__float_as_uint(a0)), "r"(__float_as_uint(a1)),
          "r"(__float_as_uint(a2)), "r"(__float_as_uint(a3)),
          "r"(__float_as_uint(b0)), "r"(__float_as_uint(b1)));
}

__device__ __forceinline__ void cp16(void* smem, const void* gmem, bool pred) {
    uint32_t s = (uint32_t)__cvta_generic_to_shared(smem);
    asm volatile("cp.async.ca.shared.global [%0], [%1], 16, %2;\n"
                 :: "r"(s), "l"(gmem), "r"(pred ? 16 : 0));
}
#define CP_COMMIT() asm volatile("cp.async.commit_group;\n")
template<int N>
__device__ __forceinline__ void cp_wait() {
    asm volatile("cp.async.wait_group %0;\n" :: "n"(N));
}

// ---------------------------------------------------------------------------
// TF32 implicit-GEMM 3x3 conv (pad 1), 3-stage cp.async pipeline for x,
// 2-stage register-prefetch for weights. (R8 proven)
// ---------------------------------------------------------------------------
template<int CIN, int MT, int EPI>
__global__ void __launch_bounds__(256)
conv_mma_kernel(const float* __restrict__ in, const float* __restrict__ w,
                const float* __restrict__ bias,
                float* __restrict__ o0, float* __restrict__ o1,
                float* __restrict__ o2)
{
    constexpr int WPAD = MT * 16 + 8;
    constexpr int NC   = CIN / 8;
    constexpr int NW   = MT * 16 * 72;
    constexpr int WREG = (NW + 255) / 256;

    extern __shared__ float dsm[];
    typedef float XBuf[6][8][136];
    typedef float WBuf[9][8][WPAD];
    XBuf* s_x = (XBuf*)dsm;                        // [3]
    WBuf* s_w = (WBuf*)(dsm + 3 * 6 * 8 * 136);    // [2]

    const int tid = threadIdx.x;
    const int warp = tid >> 5, lane = tid & 31;
    const int g = lane >> 2, tg = lane & 3;
    const int tt_w = warp >> 1;
    const int f0_w = (warp & 1) * 64;
    const int t0 = blockIdx.x * 4;
    const int b  = blockIdx.y;
    const int mg = blockIdx.z;

    for (int idx = tid; idx < 288; idx += 256) {
        int bufi = idx / 96, rem = idx % 96;
        int r = rem / 16, c = (rem >> 1) & 7, col = (rem & 1) ? 132 : 3;
        s_x[bufi][r][c][col] = 0.f;
    }

    float acc[MT][8][4];
#pragma unroll
    for (int mt = 0; mt < MT; mt++)
#pragma unroll
        for (int i = 0; i < 8; i++)
#pragma unroll
            for (int j = 0; j < 4; j++) acc[mt][i][j] = 0.f;

    auto stage_x = [&](int cb, int bufi) {
#pragma unroll
        for (int it = 0; it < 6; it++) {
            int idx = tid + it * 256;
            int v = idx & 31, rc = idx >> 5;
            int r = rc >> 3, c = rc & 7;
            int trow = t0 - 1 + r;
            bool ok = (unsigned)trow < 1024u;
            const float* src = in +
                (((long)(b * CIN + cb + c)) * 1024 + (ok ? trow : 0)) * 128 + 4 * v;
            cp16(&s_x[bufi][r][c][4 + 4 * v], src, ok);
        }
    };

    for (int idx = tid; idx < NW; idx += 256) {
        int co = idx / 72, rem = idx % 72, c = rem / 9, tap = rem % 9;
        s_w[0][tap][c][co] =
            to_tf32(w[((long)(mg * MT * 16 + co) * CIN + c) * 9 + tap]);
    }
    stage_x(0, 0);
    CP_COMMIT();
    stage_x(8, 1);
    CP_COMMIT();

    for (int ci = 0; ci < NC; ci++) {
        const int bufc = ci % 3;
        const int wbc = ci & 1, wbn = (ci + 1) & 1;

        float wreg[WREG];
        if (ci + 1 < NC) {
#pragma unroll
            for (int it = 0; it < WREG; it++) {
                int idx = tid + it * 256;
                if (idx < NW) {
                    int co = idx / 72, rem = idx % 72, c = rem / 9, tap = rem % 9;
                    wreg[it] = w[((long)(mg * MT * 16 + co) * CIN
                                  + (ci + 1) * 8 + c) * 9 + tap];
                }
            }
        }

        if (ci + 1 < NC) cp_wait<1>(); else cp_wait<0>();
        __syncthreads();

        if (ci + 2 < NC) {
            stage_x((ci + 2) * 8, (ci + 2) % 3);
            CP_COMMIT();
        }
        if (ci + 1 < NC) {
#pragma unroll
            for (int it = 0; it < WREG; it++) {
                int idx = tid + it * 256;
                if (idx < NW) {
                    int co = idx / 72, rem = idx % 72, c = rem / 9, tap = rem % 9;
                    s_w[wbn][tap][c][co] = to_tf32(wreg[it]);
                }
            }
        }

#pragma unroll
        for (int tap = 0; tap < 9; tap++) {
            const int dt = tap / 3, df = tap % 3;
            float a[MT][4];
#pragma unroll
            for (int mt = 0; mt < MT; mt++) {
                a[mt][0] = s_w[wbc][tap][tg    ][mt * 16 + g];
                a[mt][1] = s_w[wbc][tap][tg    ][mt * 16 + g + 8];
                a[mt][2] = s_w[wbc][tap][tg + 4][mt * 16 + g];
                a[mt][3] = s_w[wbc][tap][tg + 4][mt * 16 + g + 8];
            }
            const float* xr = &s_x[bufc][tt_w + dt][0][0];
#pragma unroll
            for (int i = 0; i < 8; i++) {
                int col = 3 + f0_w + i * 8 + g + df;
                float b0 = xr[tg * 136 + col];
                float b1 = xr[(tg + 4) * 136 + col];
#pragma unroll
                for (int mt = 0; mt < MT; mt++)
                    mma_tf32(acc[mt][i], a[mt][0], a[mt][1], a[mt][2], a[mt][3],
                             b0, b1);
            }
        }
    }

    const int t = t0 + tt_w;
#pragma unroll
    for (int mt = 0; mt < MT; mt++) {
        if (EPI == 0) {
            float bv0 = bias[mt * 16 + g], bv1 = bias[mt * 16 + g + 8];
            const float sc = (mt == 0) ? SCALING : 1.f;
            float* dst = (mt == 0) ? o0 : (mt == 1) ? o1 : o2;
            long base0 = (((long)(b * Hh + g    )) * Tt + t) * Ff;
            long base1 = (((long)(b * Hh + g + 8)) * Tt + t) * Ff;
#pragma unroll
            for (int i = 0; i < 8; i++) {
                int f = f0_w + i * 8 + 2 * tg;
                float2 r0, r1;
                r0.x = to_tf32(fmaxf((acc[mt][i][0] + bv0) * sc, 0.f));
                r0.y = to_tf32(fmaxf((acc[mt][i][1] + bv0) * sc, 0.f));
                r1.x = to_tf32(fmaxf((acc[mt][i][2] + bv1) * sc, 0.f));
                r1.y = to_tf32(fmaxf((acc[mt][i][3] + bv1) * sc, 0.f));
                *(float2*)(dst + base0 + f) = r0;
                *(float2*)(dst + base1 + f) = r1;
            }
        } else {
            int co0 = mg * MT * 16 + mt * 16 + g, co1 = co0 + 8;
            float bv0 = bias[co0], bv1 = bias[co1];
            long base0 = (((long)(b * 128 + co0)) * Tt + t) * Ff;
            long base1 = (((long)(b * 128 + co1)) * Tt + t) * Ff;
#pragma unroll
            for (int i = 0; i < 8; i++) {
                int f = f0_w + i * 8 + 2 * tg;
                float2 r0, r1;
                r0.x = fmaxf(acc[mt][i][0] + bv0, 0.f);
                r0.y = fmaxf(acc[mt][i][1] + bv0, 0.f);
                r1.x = fmaxf(acc[mt][i][2] + bv1, 0.f);
                r1.y = fmaxf(acc[mt][i][3] + bv1, 0.f);
                *(float2*)(o0 + base0 + f) = r0;
                *(float2*)(o0 + base1 + f) = r1;
            }
        }
    }
}

// ---------------------------------------------------------------------------
// TF32 GEMM scores = q @ k^T. BK=64 double-buffered, 512 threads,
// 4x4 warp grid, warp tile 32x32 (4 warps/SMSP for latency hiding).
// ---------------------------------------------------------------------------
__global__ void __launch_bounds__(512)
gemm_qk_kernel(const float* __restrict__ q, const float* __restrict__ kmat,
               float* __restrict__ aw)
{
    extern __shared__ float dsm[];
    typedef float TileA[128][68];
    TileA* sA = (TileA*)dsm;                    // [2]
    TileA* sB = (TileA*)(dsm + 2 * 128 * 68);   // [2]

    const int bh = blockIdx.z;
    const float* A = q    + (long)bh * Tt * Ff;
    const float* B = kmat + (long)bh * Tt * Ff;
    const int m0 = blockIdx.y * 128, n0 = blockIdx.x * 128;
    const int tid = threadIdx.x, warp = tid >> 5, lane = tid & 31;
    const int g = lane >> 2, tg = lane & 3;
    const int wm = warp >> 2, wn = warp & 3;

    float acc[2][4][4];
#pragma unroll
    for (int mt = 0; mt < 2; mt++)
#pragma unroll
        for (int i = 0; i < 4; i++)
#pragma unroll
            for (int j = 0; j < 4; j++) acc[mt][i][j] = 0.f;

    auto stage = [&](int kc, int bufi) {
#pragma unroll
        for (int it = 0; it < 4; it++) {
            int idx = tid + it * 512;
            int row = idx >> 4, q4 = (idx & 15) * 4;
            cp16(&sA[bufi][row][q4], A + (long)(m0 + row) * Ff + kc + q4, true);
            cp16(&sB[bufi][row][q4], B + (long)(n0 + row) * Ff + kc + q4, true);
        }
    };

    stage(0, 0);
    CP_COMMIT();

    for (int ci = 0; ci < 2; ci++) {
        const int bufc = ci & 1, bufn = (ci + 1) & 1;
        cp_wait<0>();
        __syncthreads();
        if (ci + 1 < 2) { stage(64, bufn); CP_COMMIT(); }

#pragma unroll
        for (int k8 = 0; k8 < 64; k8 += 8) {
            float a[2][4];
#pragma unroll
            for (int mt = 0; mt < 2; mt++) {
                int m = wm * 32 + mt * 16;
                a[mt][0] = sA[bufc][m + g    ][k8 + tg];
                a[mt][1] = sA[bufc][m + g + 8][k8 + tg];
                a[mt][2] = sA[bufc][m + g    ][k8 + tg + 4];
                a[mt][3] = sA[bufc][m + g + 8][k8 + tg + 4];
            }
#pragma unroll
            for (int i = 0; i < 4; i++) {
                int n = wn * 32 + i * 8 + g;
                float b0 = sB[bufc][n][k8 + tg];
                float b1 = sB[bufc][n][k8 + tg + 4];
#pragma unroll
                for (int mt = 0; mt < 2; mt++)
                    mma_tf32(acc[mt][i], a[mt][0], a[mt][1], a[mt][2], a[mt][3],
                             b0, b1);
            }
        }
    }

    float* C = aw + (long)bh * Tt * Tt;
#pragma unroll
    for (int mt = 0; mt < 2; mt++) {
        int m = m0 + wm * 32 + mt * 16;
#pragma unroll
        for (int i = 0; i < 4; i++) {
            int n = n0 + wn * 32 + i * 8 + 2 * tg;
            *(float2*)(C + (long)(m + g    ) * Tt + n) =
                make_float2(acc[mt][i][0], acc[mt][i][1]);
            *(float2*)(C + (long)(m + g + 8) * Tt + n) =
                make_float2(acc[mt][i][2], acc[mt][i][3]);
        }
    }
}

// ---------------------------------------------------------------------------
// TF32 GEMM attn_t = aw @ v. BK=64 double-buffered, 512 threads,
// 4x4 warp grid, warp tile 32x32. K=1024.
// ---------------------------------------------------------------------------
__global__ void __launch_bounds__(512)
gemm_av_kernel(const float* __restrict__ aw, const float* __restrict__ v,
               float* __restrict__ attn)
{
    extern __shared__ float dsm[];
    constexpr int STRIDE = 128 * 68 + 64 * 136;   // one stage: A + B
    const int bh = blockIdx.y;
    const float* A  = aw + (long)bh * Tt * Tt;
    const float* Bv = v  + (long)bh * Tt * Ff;
    const int m0 = blockIdx.x * 128;
    const int tid = threadIdx.x, warp = tid >> 5, lane = tid & 31;
    const int g = lane >> 2, tg = lane & 3;
    const int wm = warp >> 2, wn = warp & 3;

    float acc[2][4][4];
#pragma unroll
    for (int mt = 0; mt < 2; mt++)
#pragma unroll
        for (int i = 0; i < 4; i++)
#pragma unroll
            for (int j = 0; j < 4; j++) acc[mt][i][j] = 0.f;

    auto stage = [&](int kc, int bufi) {
        float* pA = dsm + bufi * STRIDE;
        float* pB = pA + 128 * 68;
#pragma unroll
        for (int it = 0; it < 4; it++) {
            int idx = tid + it * 512;
            int row = idx >> 4, q4 = (idx & 15) * 4;
            cp16(&pA[row * 68 + q4], A + (long)(m0 + row) * Tt + kc + q4, true);
            int kr = idx >> 5, vv = (idx & 31) * 4;
            cp16(&pB[kr * 136 + vv], Bv + (long)(kc + kr) * Ff + vv, true);
        }
    };

    stage(0, 0);
    CP_COMMIT();

    for (int ci = 0; ci < 16; ci++) {
        const int bufc = ci & 1;
        const float* sA = dsm + bufc * STRIDE;
        const float* sB = sA + 128 * 68;

        cp_wait<0>();
        __syncthreads();
        if (ci + 1 < 16) { stage((ci + 1) * 64, bufc ^ 1); CP_COMMIT(); }

#pragma unroll
        for (int k8 = 0; k8 < 64; k8 += 8) {
            float a[2][4];
#pragma unroll
            for (int mt = 0; mt < 2; mt++) {
                int m = wm * 32 + mt * 16;
                a[mt][0] = sA[(m + g    ) * 68 + k8 + tg];
                a[mt][1] = sA[(m + g + 8) * 68 + k8 + tg];
                a[mt][2] = sA[(m + g    ) * 68 + k8 + tg + 4];
                a[mt][3] = sA[(m + g + 8) * 68 + k8 + tg + 4];
            }
#pragma unroll
            for (int i = 0; i < 4; i++) {
                int n = wn * 32 + i * 8 + g;
                float b0 = sB[(k8 + tg    ) * 136 + n];
                float b1 = sB[(k8 + tg + 4) * 136 + n];
#pragma unroll
                for (int mt = 0; mt < 2; mt++)
                    mma_tf32(acc[mt][i], a[mt][0], a[mt][1], a[mt][2], a[mt][3],
                             b0, b1);
            }
        }
    }

    const int b = bh >> 4, h = bh & 15;
    float* C = attn + ((long)(b * 32 + h)) * Tt * Ff;
#pragma unroll
    for (int mt = 0; mt < 2; mt++) {
        int m = m0 + wm * 32 + mt * 16;
#pragma unroll
        for (int i = 0; i < 4; i++) {
            int n = wn * 32 + i * 8 + 2 * tg;
            *(float2*)(C + (long)(m + g    ) * Ff + n) =
                make_float2(to_tf32(acc[mt][i][0]), to_tf32(acc[mt][i][1]));
            *(float2*)(C + (long)(m + g + 8) * Ff + n) =
                make_float2(to_tf32(acc[mt][i][2]), to_tf32(acc[mt][i][3]));
        }
    }
}

// ---------------------------------------------------------------------------
// TF32 GEMM pf partials = q^T @ k (split-K x4, 2-stage). M=N=128, Kseg=256.
// ---------------------------------------------------------------------------
__global__ void __launch_bounds__(256, 2)
gemm_qtk_kernel(const float* __restrict__ q, const float* __restrict__ kmat,
                float* __restrict__ pfp)
{
    extern __shared__ float dsm[];
    typedef float Tile[32][132];
    Tile* sA = (Tile*)dsm;
    Tile* sB = (Tile*)(dsm + 2 * 32 * 132);

    const int seg = blockIdx.x, bh = blockIdx.y;
    const float* A = q    + (long)bh * Tt * Ff;
    const float* B = kmat + (long)bh * Tt * Ff;
    const int k0 = seg * 256;
    const int tid = threadIdx.x, warp = tid >> 5, lane = tid & 31;
    const int g = lane >> 2, tg = lane & 3;
    const int wm = warp >> 1, wn = warp & 1;

    float acc[2][8][4];
#pragma unroll
    for (int mt = 0; mt < 2; mt++)
#pragma unroll
        for (int i = 0; i < 8; i++)
#pragma unroll
            for (int j = 0; j < 4; j++) acc[mt][i][j] = 0.f;

    auto stage = [&](int kc, int bufi) {
#pragma unroll
        for (int it = 0; it < 4; it++) {
            int idx = tid + it * 256;
            int kk = idx >> 5, c4 = (idx & 31) * 4;
            cp16(&sA[bufi][kk][c4], A + (long)(k0 + kc + kk) * Ff + c4, true);
            cp16(&sB[bufi][kk][c4], B + (long)(k0 + kc + kk) * Ff + c4, true);
        }
    };

    stage(0, 0);
    CP_COMMIT();

    for (int ci = 0; ci < 8; ci++) {
        const int bufc = ci & 1, bufn = (ci + 1) & 1;
        cp_wait<0>();
        __syncthreads();
        if (ci + 1 < 8) { stage((ci + 1) * 32, bufn); CP_COMMIT(); }

#pragma unroll
        for (int k8 = 0; k8 < 32; k8 += 8) {
            float a[2][4];
#pragma unroll
            for (int mt = 0; mt < 2; mt++) {
                int m = wm * 32 + mt * 16;
                a[mt][0] = sA[bufc][k8 + tg    ][m + g];
                a[mt][1] = sA[bufc][k8 + tg    ][m + g + 8];
                a[mt][2] = sA[bufc][k8 + tg + 4][m + g];
                a[mt][3] = sA[bufc][k8 + tg + 4][m + g + 8];
            }
#pragma unroll
            for (int i = 0; i < 8; i++) {
                int n = wn * 64 + i * 8 + g;
                float b0 = sB[bufc][k8 + tg    ][n];
                float b1 = sB[bufc][k8 + tg + 4][n];
#pragma unroll
                for (int mt = 0; mt < 2; mt++)
                    mma_tf32(acc[mt][i], a[mt][0], a[mt][1], a[mt][2], a[mt][3],
                             b0, b1);
            }
        }
    }

    float* C = pfp + ((long)(seg * BH + bh)) * Ff * Ff;
#pragma unroll
    for (int mt = 0; mt < 2; mt++) {
        int m = wm * 32 + mt * 16;
#pragma unroll
        for (int i = 0; i < 8; i++) {
            int n = wn * 64 + i * 8 + 2 * tg;
            *(float2*)(C + (long)(m + g    ) * Ff + n) =
                make_float2(acc[mt][i][0], acc[mt][i][1]);
            *(float2*)(C + (long)(m + g + 8) * Ff + n) =
                make_float2(acc[mt][i][2], acc[mt][i][3]);
        }
    }
}

// ---------------------------------------------------------------------------
// sum 4 split-K partials, softmax, tf32-round -> pf. Block = one row.
// ---------------------------------------------------------------------------
__global__ void __launch_bounds__(128)
softmax_f_kernel(const float* __restrict__ pfp, float* __restrict__ pf)
{
    const int r = blockIdx.x;          // bh*128 + row
    const int bh = r >> 7, rr = r & 127;
    const int tid = threadIdx.x, lane = tid & 31, w = tid >> 5;
    __shared__ float red[4];
    __shared__ float bc;

    float v = 0.f;
#pragma unroll
    for (int seg = 0; seg < 4; seg++)
        v += pfp[(((long)(seg * BH + bh)) * Ff + rr) * Ff + tid];

    float m = v;
#pragma unroll
    for (int o = 16; o > 0; o >>= 1) m = fmaxf(m, __shfl_xor_sync(~0u, m, o));
    if (lane == 0) red[w] = m;
    __syncthreads();
    if (tid == 0) bc = fmaxf(fmaxf(red[0], red[1]), fmaxf(red[2], red[3]));
    __syncthreads();
    m = bc;
    float e = __expf(v - m);
    float s = e;
#pragma unroll
    for (int o = 16; o > 0; o >>= 1) s += __shfl_xor_sync(~0u, s, o);
    __syncthreads();
    if (lane == 0) red[w] = s;
    __syncthreads();
    if (tid == 0) bc = 1.f / (red[0] + red[1] + red[2] + red[3]);
    __syncthreads();
    pf[(long)r * Ff + tid] = to_tf32(e * bc);
}

// ---------------------------------------------------------------------------
// TF32 GEMM attn_f^T = v @ pf^T (2-stage pipelined). M=1024, N=128, K=128.
// ---------------------------------------------------------------------------
__global__ void __launch_bounds__(256, 2)
gemm_vp_kernel(const float* __restrict__ v, const float* __restrict__ pf,
               float* __restrict__ attn)
{
    extern __shared__ float dsm[];
    typedef float TileA[128][36];
    TileA* sA = (TileA*)dsm;
    TileA* sB = (TileA*)(dsm + 2 * 128 * 36);

    const int bh = blockIdx.y;
    const float* A = v  + (long)bh * Tt * Ff;
    const float* B = pf + (long)bh * Ff * Ff;
    const int m0 = blockIdx.x * 128;
    const int tid = threadIdx.x, warp = tid >> 5, lane = tid & 31;
    const int g = lane >> 2, tg = lane & 3;
    const int wm = warp >> 1, wn = warp & 1;

    float acc[2][8][4];
#pragma unroll
    for (int mt = 0; mt < 2; mt++)
#pragma unroll
        for (int i = 0; i < 8; i++)
#pragma unroll
            for (int j = 0; j < 4; j++) acc[mt][i][j] = 0.f;

    auto stage = [&](int kc, int bufi) {
#pragma unroll
        for (int it = 0; it < 4; it++) {
            int idx = tid + it * 256;
            int row = idx >> 3, q4 = (idx & 7) * 4;
            cp16(&sA[bufi][row][q4], A + (long)(m0 + row) * Ff + kc + q4, true);
            cp16(&sB[bufi][row][q4], B + (long)row * Ff + kc + q4, true);
        }
    };

    stage(0, 0);
    CP_COMMIT();

    for (int ci = 0; ci < 4; ci++) {
        const int bufc = ci & 1, bufn = (ci + 1) & 1;
        cp_wait<0>();
        __syncthreads();
        if (ci + 1 < 4) { stage((ci + 1) * 32, bufn); CP_COMMIT(); }

#pragma unroll
        for (int k8 = 0; k8 < 32; k8 += 8) {
            float a[2][4];
#pragma unroll
            for (int mt = 0; mt < 2; mt++) {
                int m = wm * 32 + mt * 16;
                a[mt][0] = sA[bufc][m + g    ][k8 + tg];
                a[mt][1] = sA[bufc][m + g + 8][k8 + tg];
                a[mt][2] = sA[bufc][m + g    ][k8 + tg + 4];
                a[mt][3] = sA[bufc][m + g + 8][k8 + tg + 4];
            }
#pragma unroll
            for (int i = 0; i < 8; i++) {
                int n = wn * 64 + i * 8 + g;
                float b0 = sB[bufc][n][k8 + tg];
                float b1 = sB[bufc][n][k8 + tg + 4];
#pragma unroll
                for (int mt = 0; mt < 2; mt++)
                    mma_tf32(acc[mt][i], a[mt][0], a[mt][1], a[mt][2], a[mt][3],
                             b0, b1);
            }
        }
    }

    const int b = bh >> 4, h = bh & 15;
    float* C = attn + ((long)(b * 32 + 16 + h)) * Tt * Ff;
#pragma unroll
    for (int mt = 0; mt < 2; mt++) {
        int m = m0 + wm * 32 + mt * 16;
#pragma unroll
        for (int i = 0; i < 8; i++) {
            int n = wn * 64 + i * 8 + 2 * tg;
            *(float2*)(C + (long)(m + g    ) * Ff + n) =
                make_float2(to_tf32(acc[mt][i][0]), to_tf32(acc[mt][i][1]));
            *(float2*)(C + (long)(m + g + 8) * Ff + n) =
                make_float2(to_tf32(acc[mt][i][2]), to_tf32(acc[mt][i][3]));
        }
    }
}

// ---------------------------------------------------------------------------
// Fused softmax (warp-per-head) + head-average. Block = (t, b), 512 threads.
// ---------------------------------------------------------------------------
__global__ void __launch_bounds__(512)
softmax_avg_kernel(float* __restrict__ aw, float* __restrict__ avg)
{
    extern __shared__ float se[];   // [16][1024]
    const int t = blockIdx.x, b = blockIdx.y;
    const int h = threadIdx.x >> 5, lane = threadIdx.x & 31;

    float4* row = reinterpret_cast<float4*>(
        aw + (((long)(b * Hh + h)) * Tt + t) * Tt);
    float4 v[8];
    float m = -1e30f;
#pragma unroll
    for (int j = 0; j < 8; j++) {
        v[j] = row[lane + 32 * j];
        m = fmaxf(m, fmaxf(fmaxf(v[j].x, v[j].y), fmaxf(v[j].z, v[j].w)));
    }
#pragma unroll
    for (int o = 16; o > 0; o >>= 1) m = fmaxf(m, __shfl_xor_sync(~0u, m, o));

    float s = 0.f;
#pragma unroll
    for (int j = 0; j < 8; j++) {
        v[j].x = __expf(v[j].x - m); v[j].y = __expf(v[j].y - m);
        v[j].z = __expf(v[j].z - m); v[j].w = __expf(v[j].w - m);
        s += v[j].x + v[j].y + v[j].z + v[j].w;
    }
#pragma unroll
    for (int o = 16; o > 0; o >>= 1) s += __shfl_xor_sync(~0u, s, o);
    const float inv = 1.f / s;

    float4* sh = reinterpret_cast<float4*>(se + h * 1024);
#pragma unroll
    for (int j = 0; j < 8; j++) {
        float4 e;
        e.x = to_tf32(v[j].x * inv); e.y = to_tf32(v[j].y * inv);
        e.z = to_tf32(v[j].z * inv); e.w = to_tf32(v[j].w * inv);
        row[lane + 32 * j] = e;
        sh[lane + 32 * j]  = e;
    }
    __syncthreads();

    float* op = avg + ((long)b * Tt + t) * Tt;
    for (int col = threadIdx.x; col < 1024; col += 512) {
        float a = 0.f;
#pragma unroll
        for (int hh = 0; hh < 16; hh++) a += se[hh * 1024 + col];
        op[col] = a * (1.f / 16.f);
    }
}

// ---------------------------------------------------------------------------
extern "C" void kernel_launch(void* const* d_in, const int* in_sizes, int n_in,
                              void* d_out, int out_size)
{
    const float* query = (const float*)d_in[0];
    const float* in_w  = (const float*)d_in[1];
    const float* in_b  = (const float*)d_in[2];
    const float* out_w = (const float*)d_in[3];
    const float* out_b = (const float*)d_in[4];

    float* out    = (float*)d_out;
    float* aw_avg = out + (long)Bsz * 128 * Tt * Ff;

    float *q, *k, *v, *aw, *attn, *pf, *pfp;
    cudaGetSymbolAddress((void**)&q,    g_q);
    cudaGetSymbolAddress((void**)&k,    g_k);
    cudaGetSymbolAddress((void**)&v,    g_v);
    cudaGetSymbolAddress((void**)&aw,   g_aw);
    cudaGetSymbolAddress((void**)&attn, g_attn);
    cudaGetSymbolAddress((void**)&pf,   g_pf);
    cudaGetSymbolAddress((void**)&pfp,  g_pfp);

    const int smem_conv_in  = (3 * 6 * 8 * 136 + 2 * 9 * 8 * 56) * 4;
    const int smem_conv_out = (3 * 6 * 8 * 136 + 2 * 9 * 8 * 40) * 4;
    const int smem_qk       = (2 * 128 * 68 * 2) * 4;                 // 139264
    const int smem_av       = (2 * (128 * 68 + 64 * 136)) * 4;        // 139264
    const int smem_qtk      = (2 * 32 * 132 * 2) * 4;
    const int smem_vp       = (2 * 128 * 36 * 2) * 4;
    const int smem_sm       = 16 * 1024 * 4;

    cudaFuncSetAttribute(conv_mma_kernel<128, 3, 0>,
        cudaFuncAttributeMaxDynamicSharedMemorySize, smem_conv_in);
    cudaFuncSetAttribute(conv_mma_kernel<32, 2, 1>,
        cudaFuncAttributeMaxDynamicSharedMemorySize, smem_conv_out);
    cudaFuncSetAttribute(gemm_qk_kernel,
        cudaFuncAttributeMaxDynamicSharedMemorySize, smem_qk);
    cudaFuncSetAttribute(gemm_av_kernel,
        cudaFuncAttributeMaxDynamicSharedMemorySize, smem_av);
    cudaFuncSetAttribute(gemm_qtk_kernel,
        cudaFuncAttributeMaxDynamicSharedMemorySize, smem_qtk);
    cudaFuncSetAttribute(gemm_vp_kernel,
        cudaFuncAttributeMaxDynamicSharedMemorySize, smem_vp);
    cudaFuncSetAttribute(softmax_avg_kernel,
        cudaFuncAttributeMaxDynamicSharedMemorySize, smem_sm);

    // 1. fused qkv conv — raw query (mma truncates x operand to tf32)
    conv_mma_kernel<128, 3, 0><<<dim3(256, 4, 1), 256, smem_conv_in>>>(
        query, in_w, in_b, q, k, v);
    // 2. time scores (BK=64, 512 threads)
    gemm_qk_kernel<<<dim3(8, 8, BH), 512, smem_qk>>>(q, k, aw);
    // 3. fused softmax + head-avg
    softmax_avg_kernel<<<dim3(1024, Bsz), 512, smem_sm>>>(aw, aw_avg);
    // 4. attn_t = aw @ v (BK=64, 512 threads) -> channels [0:16)
    gemm_av_kernel<<<dim3(8, BH), 512, smem_av>>>(aw, v, attn);
    // 5. freq scores (split-K x4)
    gemm_qtk_kernel<<<dim3(4, BH), 256, smem_qtk>>>(q, k, pfp);
    // 6. sum partials + softmax
    softmax_f_kernel<<<BH * Ff, 128>>>(pfp, pf);
    // 7. attn_f^T = v @ pf^T -> channels [16:32)
    gemm_vp_kernel<<<dim3(8, BH), 256, smem_vp>>>(v, pf, attn);
    // 8. output conv (3-stage x pipeline)
    conv_mma_kernel<32, 2, 1><<<dim3(256, 4, 4), 256, smem_conv_out>>>(
        attn, out_w, out_b, out, nullptr, nullptr);
}

// round 14
// speedup vs baseline: 1.0161x; 1.0161x over previous
#include <cuda_runtime.h>
#include <cuda_bf16.h>
#include <cstdint>

#define Bsz 4
#define Hh  16
#define Tt  1024
#define Ff  128
#define BH  64

static const float SCALING = 0.08838834764831845f; // 128^-0.5

__device__ float g_q   [(long)BH * Tt * Ff];
__device__ float g_k   [(long)BH * Tt * Ff];
__device__ float g_v   [(long)BH * Tt * Ff];
__device__ float g_aw  [(long)BH * Tt * Tt];
__device__ float g_attn[(long)Bsz * 32 * Tt * Ff];
__device__ float g_pf  [(long)BH * Ff * Ff];
__device__ float g_pfp [(long)4 * BH * Ff * Ff]; // split-K partials

// streams/events created once at load time (outside graph capture)
static cudaStream_t g_s1;
static cudaEvent_t  g_ev_fork, g_ev_join;
static struct StreamInit {
    StreamInit() {
        cudaStreamCreateWithFlags(&g_s1, cudaStreamNonBlocking);
        cudaEventCreateWithFlags(&g_ev_fork, cudaEventDisableTiming);
        cudaEventCreateWithFlags(&g_ev_join, cudaEventDisableTiming);
    }
} g_stream_init;

__device__ __forceinline__ float to_tf32(float x) {
    uint32_t u;
    asm("cvt.rna.tf32.f32 %0, %1;" : "=r"(u) : "f"(x));
    return __uint_as_float(u);
}
__device__ __forceinline__ void mma_tf32(float* d, float a0, float a1,
                                         float a2, float a3, float b0, float b1)
{
    asm volatile(
        "mma.sync.aligned.m16n8k8.row.col.f32.tf32.tf32.f32 "
        "{%0,%1,%2,%3}, {%4,%5,%6,%7}, {%8,%9}, {%0,%1,%2,%3};\n"
        : "+f"(d[0]), "+f"(d[1]), "+f"(d[2]), "+f"(d[3])
        : "r"(__float_as_uint(a0)), "r"(__float_as_uint(a1)),
          "r"(__float_as_uint(a2)), "r"(__float_as_uint(a3)),
          "r"(__float_as_uint(b0)), "r"(__float_as_uint(b1)));
}

__device__ __forceinline__ void cp16(void* smem, const void* gmem, bool pred) {
    uint32_t s = (uint32_t)__cvta_generic_to_shared(smem);
    asm volatile("cp.async.ca.shared.global [%0], [%1], 16, %2;\n"
                 :: "r"(s), "l"(gmem), "r"(pred ? 16 : 0));
}
#define CP_COMMIT() asm volatile("cp.async.commit_group;\n")
template<int N>
__device__ __forceinline__ void cp_wait() {
    asm volatile("cp.async.wait_group %0;\n" :: "n"(N));
}

// ---------------------------------------------------------------------------
// TF32 implicit-GEMM 3x3 conv (pad 1), 3-stage cp.async pipeline for x,
// 2-stage register-prefetch for weights. (R8 proven)
// ---------------------------------------------------------------------------
template<int CIN, int MT, int EPI>
__global__ void __launch_bounds__(256)
conv_mma_kernel(const float* __restrict__ in, const float* __restrict__ w,
                const float* __restrict__ bias,
                float* __restrict__ o0, float* __restrict__ o1,
                float* __restrict__ o2)
{
    constexpr int WPAD = MT * 16 + 8;
    constexpr int NC   = CIN / 8;
    constexpr int NW   = MT * 16 * 72;
    constexpr int WREG = (NW + 255) / 256;

    extern __shared__ float dsm[];
    typedef float XBuf[6][8][136];
    typedef float WBuf[9][8][WPAD];
    XBuf* s_x = (XBuf*)dsm;                        // [3]
    WBuf* s_w = (WBuf*)(dsm + 3 * 6 * 8 * 136);    // [2]

    const int tid = threadIdx.x;
    const int warp = tid >> 5, lane = tid & 31;
    const int g = lane >> 2, tg = lane & 3;
    const int tt_w = warp >> 1;
    const int f0_w = (warp & 1) * 64;
    const int t0 = blockIdx.x * 4;
    const int b  = blockIdx.y;
    const int mg = blockIdx.z;

    for (int idx = tid; idx < 288; idx += 256) {
        int bufi = idx / 96, rem = idx % 96;
        int r = rem / 16, c = (rem >> 1) & 7, col = (rem & 1) ? 132 : 3;
        s_x[bufi][r][c][col] = 0.f;
    }

    float acc[MT][8][4];
#pragma unroll
    for (int mt = 0; mt < MT; mt++)
#pragma unroll
        for (int i = 0; i < 8; i++)
#pragma unroll
            for (int j = 0; j < 4; j++) acc[mt][i][j] = 0.f;

    auto stage_x = [&](int cb, int bufi) {
#pragma unroll
        for (int it = 0; it < 6; it++) {
            int idx = tid + it * 256;
            int v = idx & 31, rc = idx >> 5;
            int r = rc >> 3, c = rc & 7;
            int trow = t0 - 1 + r;
            bool ok = (unsigned)trow < 1024u;
            const float* src = in +
                (((long)(b * CIN + cb + c)) * 1024 + (ok ? trow : 0)) * 128 + 4 * v;
            cp16(&s_x[bufi][r][c][4 + 4 * v], src, ok);
        }
    };

    for (int idx = tid; idx < NW; idx += 256) {
        int co = idx / 72, rem = idx % 72, c = rem / 9, tap = rem % 9;
        s_w[0][tap][c][co] =
            to_tf32(w[((long)(mg * MT * 16 + co) * CIN + c) * 9 + tap]);
    }
    stage_x(0, 0);
    CP_COMMIT();
    stage_x(8, 1);
    CP_COMMIT();

    for (int ci = 0; ci < NC; ci++) {
        const int bufc = ci % 3;
        const int wbc = ci & 1, wbn = (ci + 1) & 1;

        float wreg[WREG];
        if (ci + 1 < NC) {
#pragma unroll
            for (int it = 0; it < WREG; it++) {
                int idx = tid + it * 256;
                if (idx < NW) {
                    int co = idx / 72, rem = idx % 72, c = rem / 9, tap = rem % 9;
                    wreg[it] = w[((long)(mg * MT * 16 + co) * CIN
                                  + (ci + 1) * 8 + c) * 9 + tap];
                }
            }
        }

        if (ci + 1 < NC) cp_wait<1>(); else cp_wait<0>();
        __syncthreads();

        if (ci + 2 < NC) {
            stage_x((ci + 2) * 8, (ci + 2) % 3);
            CP_COMMIT();
        }
        if (ci + 1 < NC) {
#pragma unroll
            for (int it = 0; it < WREG; it++) {
                int idx = tid + it * 256;
                if (idx < NW) {
                    int co = idx / 72, rem = idx % 72, c = rem / 9, tap = rem % 9;
                    s_w[wbn][tap][c][co] = to_tf32(wreg[it]);
                }
            }
        }

#pragma unroll
        for (int tap = 0; tap < 9; tap++) {
            const int dt = tap / 3, df = tap % 3;
            float a[MT][4];
#pragma unroll
            for (int mt = 0; mt < MT; mt++) {
                a[mt][0] = s_w[wbc][tap][tg    ][mt * 16 + g];
                a[mt][1] = s_w[wbc][tap][tg    ][mt * 16 + g + 8];
                a[mt][2] = s_w[wbc][tap][tg + 4][mt * 16 + g];
                a[mt][3] = s_w[wbc][tap][tg + 4][mt * 16 + g + 8];
            }
            const float* xr = &s_x[bufc][tt_w + dt][0][0];
#pragma unroll
            for (int i = 0; i < 8; i++) {
                int col = 3 + f0_w + i * 8 + g + df;
                float b0 = xr[tg * 136 + col];
                float b1 = xr[(tg + 4) * 136 + col];
#pragma unroll
                for (int mt = 0; mt < MT; mt++)
                    mma_tf32(acc[mt][i], a[mt][0], a[mt][1], a[mt][2], a[mt][3],
                             b0, b1);
            }
        }
    }

    const int t = t0 + tt_w;
#pragma unroll
    for (int mt = 0; mt < MT; mt++) {
        if (EPI == 0) {
            float bv0 = bias[mt * 16 + g], bv1 = bias[mt * 16 + g + 8];
            const float sc = (mt == 0) ? SCALING : 1.f;
            float* dst = (mt == 0) ? o0 : (mt == 1) ? o1 : o2;
            long base0 = (((long)(b * Hh + g    )) * Tt + t) * Ff;
            long base1 = (((long)(b * Hh + g + 8)) * Tt + t) * Ff;
#pragma unroll
            for (int i = 0; i < 8; i++) {
                int f = f0_w + i * 8 + 2 * tg;
                float2 r0, r1;
                r0.x = to_tf32(fmaxf((acc[mt][i][0] + bv0) * sc, 0.f));
                r0.y = to_tf32(fmaxf((acc[mt][i][1] + bv0) * sc, 0.f));
                r1.x = to_tf32(fmaxf((acc[mt][i][2] + bv1) * sc, 0.f));
                r1.y = to_tf32(fmaxf((acc[mt][i][3] + bv1) * sc, 0.f));
                *(float2*)(dst + base0 + f) = r0;
                *(float2*)(dst + base1 + f) = r1;
            }
        } else {
            int co0 = mg * MT * 16 + mt * 16 + g, co1 = co0 + 8;
            float bv0 = bias[co0], bv1 = bias[co1];
            long base0 = (((long)(b * 128 + co0)) * Tt + t) * Ff;
            long base1 = (((long)(b * 128 + co1)) * Tt + t) * Ff;
#pragma unroll
            for (int i = 0; i < 8; i++) {
                int f = f0_w + i * 8 + 2 * tg;
                float2 r0, r1;
                r0.x = fmaxf(acc[mt][i][0] + bv0, 0.f);
                r0.y = fmaxf(acc[mt][i][1] + bv0, 0.f);
                r1.x = fmaxf(acc[mt][i][2] + bv1, 0.f);
                r1.y = fmaxf(acc[mt][i][3] + bv1, 0.f);
                *(float2*)(o0 + base0 + f) = r0;
                *(float2*)(o0 + base1 + f) = r1;
            }
        }
    }
}

// ---------------------------------------------------------------------------
// TF32 GEMM scores = q @ k^T. BK=64, double-buffered, 256 thr (R11 best).
// ---------------------------------------------------------------------------
__global__ void __launch_bounds__(256)
gemm_qk_kernel(const float* __restrict__ q, const float* __restrict__ kmat,
               float* __restrict__ aw)
{
    extern __shared__ float dsm[];
    typedef float TileA[128][68];
    TileA* sA = (TileA*)dsm;                    // [2]
    TileA* sB = (TileA*)(dsm + 2 * 128 * 68);   // [2]

    const int bh = blockIdx.z;
    const float* A = q    + (long)bh * Tt * Ff;
    const float* B = kmat + (long)bh * Tt * Ff;
    const int m0 = blockIdx.y * 128, n0 = blockIdx.x * 128;
    const int tid = threadIdx.x, warp = tid >> 5, lane = tid & 31;
    const int g = lane >> 2, tg = lane & 3;
    const int wm = warp >> 1, wn = warp & 1;

    float acc[2][8][4];
#pragma unroll
    for (int mt = 0; mt < 2; mt++)
#pragma unroll
        for (int i = 0; i < 8; i++)
#pragma unroll
            for (int j = 0; j < 4; j++) acc[mt][i][j] = 0.f;

    auto stage = [&](int kc, int bufi) {
#pragma unroll
        for (int it = 0; it < 8; it++) {
            int idx = tid + it * 256;
            int row = idx >> 4, q4 = (idx & 15) * 4;
            cp16(&sA[bufi][row][q4], A + (long)(m0 + row) * Ff + kc + q4, true);
            cp16(&sB[bufi][row][q4], B + (long)(n0 + row) * Ff + kc + q4, true);
        }
    };

    stage(0, 0);
    CP_COMMIT();

    for (int ci = 0; ci < 2; ci++) {
        const int bufc = ci & 1, bufn = (ci + 1) & 1;
        cp_wait<0>();
        __syncthreads();
        if (ci + 1 < 2) { stage(64, bufn); CP_COMMIT(); }

#pragma unroll
        for (int k8 = 0; k8 < 64; k8 += 8) {
            float a[2][4];
#pragma unroll
            for (int mt = 0; mt < 2; mt++) {
                int m = wm * 32 + mt * 16;
                a[mt][0] = sA[bufc][m + g    ][k8 + tg];
                a[mt][1] = sA[bufc][m + g + 8][k8 + tg];
                a[mt][2] = sA[bufc][m + g    ][k8 + tg + 4];
                a[mt][3] = sA[bufc][m + g + 8][k8 + tg + 4];
            }
#pragma unroll
            for (int i = 0; i < 8; i++) {
                int n = wn * 64 + i * 8 + g;
                float b0 = sB[bufc][n][k8 + tg];
                float b1 = sB[bufc][n][k8 + tg + 4];
#pragma unroll
                for (int mt = 0; mt < 2; mt++)
                    mma_tf32(acc[mt][i], a[mt][0], a[mt][1], a[mt][2], a[mt][3],
                             b0, b1);
            }
        }
    }

    float* C = aw + (long)bh * Tt * Tt;
#pragma unroll
    for (int mt = 0; mt < 2; mt++) {
        int m = m0 + wm * 32 + mt * 16;
#pragma unroll
        for (int i = 0; i < 8; i++) {
            int n = n0 + wn * 64 + i * 8 + 2 * tg;
            *(float2*)(C + (long)(m + g    ) * Tt + n) =
                make_float2(acc[mt][i][0], acc[mt][i][1]);
            *(float2*)(C + (long)(m + g + 8) * Tt + n) =
                make_float2(acc[mt][i][2], acc[mt][i][3]);
        }
    }
}

// ---------------------------------------------------------------------------
// TF32 GEMM attn_t = aw @ v. BK=64, double-buffered, 256 thr (R11 best).
// ---------------------------------------------------------------------------
__global__ void __launch_bounds__(256)
gemm_av_kernel(const float* __restrict__ aw, const float* __restrict__ v,
               float* __restrict__ attn)
{
    extern __shared__ float dsm[];
    constexpr int STRIDE = 128 * 68 + 64 * 136;   // one stage: A + B
    const int bh = blockIdx.y;
    const float* A  = aw + (long)bh * Tt * Tt;
    const float* Bv = v  + (long)bh * Tt * Ff;
    const int m0 = blockIdx.x * 128;
    const int tid = threadIdx.x, warp = tid >> 5, lane = tid & 31;
    const int g = lane >> 2, tg = lane & 3;
    const int wm = warp >> 1, wn = warp & 1;

    float acc[2][8][4];
#pragma unroll
    for (int mt = 0; mt < 2; mt++)
#pragma unroll
        for (int i = 0; i < 8; i++)
#pragma unroll
            for (int j = 0; j < 4; j++) acc[mt][i][j] = 0.f;

    auto stage = [&](int kc, int bufi) {
        float* pA = dsm + bufi * STRIDE;
        float* pB = pA + 128 * 68;
#pragma unroll
        for (int it = 0; it < 8; it++) {
            int idx = tid + it * 256;
            int row = idx >> 4, q4 = (idx & 15) * 4;
            cp16(&pA[row * 68 + q4], A + (long)(m0 + row) * Tt + kc + q4, true);
            int kr = idx >> 5, vv = (idx & 31) * 4;
            cp16(&pB[kr * 136 + vv], Bv + (long)(kc + kr) * Ff + vv, true);
        }
    };

    stage(0, 0);
    CP_COMMIT();

    for (int ci = 0; ci < 16; ci++) {
        const int bufc = ci & 1;
        const float* sA = dsm + bufc * STRIDE;
        const float* sB = sA + 128 * 68;

        cp_wait<0>();
        __syncthreads();
        if (ci + 1 < 16) { stage((ci + 1) * 64, bufc ^ 1); CP_COMMIT(); }

#pragma unroll
        for (int k8 = 0; k8 < 64; k8 += 8) {
            float a[2][4];
#pragma unroll
            for (int mt = 0; mt < 2; mt++) {
                int m = wm * 32 + mt * 16;
                a[mt][0] = sA[(m + g    ) * 68 + k8 + tg];
                a[mt][1] = sA[(m + g + 8) * 68 + k8 + tg];
                a[mt][2] = sA[(m + g    ) * 68 + k8 + tg + 4];
                a[mt][3] = sA[(m + g + 8) * 68 + k8 + tg + 4];
            }
#pragma unroll
            for (int i = 0; i < 8; i++) {
                int n = wn * 64 + i * 8 + g;
                float b0 = sB[(k8 + tg    ) * 136 + n];
                float b1 = sB[(k8 + tg + 4) * 136 + n];
#pragma unroll
                for (int mt = 0; mt < 2; mt++)
                    mma_tf32(acc[mt][i], a[mt][0], a[mt][1], a[mt][2], a[mt][3],
                             b0, b1);
            }
        }
    }

    const int b = bh >> 4, h = bh & 15;
    float* C = attn + ((long)(b * 32 + h)) * Tt * Ff;
#pragma unroll
    for (int mt = 0; mt < 2; mt++) {
        int m = m0 + wm * 32 + mt * 16;
#pragma unroll
        for (int i = 0; i < 8; i++) {
            int n = wn * 64 + i * 8 + 2 * tg;
            *(float2*)(C + (long)(m + g    ) * Ff + n) =
                make_float2(to_tf32(acc[mt][i][0]), to_tf32(acc[mt][i][1]));
            *(float2*)(C + (long)(m + g + 8) * Ff + n) =
                make_float2(to_tf32(acc[mt][i][2]), to_tf32(acc[mt][i][3]));
        }
    }
}

// ---------------------------------------------------------------------------
// TF32 GEMM pf partials = q^T @ k (split-K x4, 2-stage). M=N=128, Kseg=256.
// ---------------------------------------------------------------------------
__global__ void __launch_bounds__(256, 2)
gemm_qtk_kernel(const float* __restrict__ q, const float* __restrict__ kmat,
                float* __restrict__ pfp)
{
    extern __shared__ float dsm[];
    typedef float Tile[32][132];
    Tile* sA = (Tile*)dsm;
    Tile* sB = (Tile*)(dsm + 2 * 32 * 132);

    const int seg = blockIdx.x, bh = blockIdx.y;
    const float* A = q    + (long)bh * Tt * Ff;
    const float* B = kmat + (long)bh * Tt * Ff;
    const int k0 = seg * 256;
    const int tid = threadIdx.x, warp = tid >> 5, lane = tid & 31;
    const int g = lane >> 2, tg = lane & 3;
    const int wm = warp >> 1, wn = warp & 1;

    float acc[2][8][4];
#pragma unroll
    for (int mt = 0; mt < 2; mt++)
#pragma unroll
        for (int i = 0; i < 8; i++)
#pragma unroll
            for (int j = 0; j < 4; j++) acc[mt][i][j] = 0.f;

    auto stage = [&](int kc, int bufi) {
#pragma unroll
        for (int it = 0; it < 4; it++) {
            int idx = tid + it * 256;
            int kk = idx >> 5, c4 = (idx & 31) * 4;
            cp16(&sA[bufi][kk][c4], A + (long)(k0 + kc + kk) * Ff + c4, true);
            cp16(&sB[bufi][kk][c4], B + (long)(k0 + kc + kk) * Ff + c4, true);
        }
    };

    stage(0, 0);
    CP_COMMIT();

    for (int ci = 0; ci < 8; ci++) {
        const int bufc = ci & 1, bufn = (ci + 1) & 1;
        cp_wait<0>();
        __syncthreads();
        if (ci + 1 < 8) { stage((ci + 1) * 32, bufn); CP_COMMIT(); }

#pragma unroll
        for (int k8 = 0; k8 < 32; k8 += 8) {
            float a[2][4];
#pragma unroll
            for (int mt = 0; mt < 2; mt++) {
                int m = wm * 32 + mt * 16;
                a[mt][0] = sA[bufc][k8 + tg    ][m + g];
                a[mt][1] = sA[bufc][k8 + tg    ][m + g + 8];
                a[mt][2] = sA[bufc][k8 + tg + 4][m + g];
                a[mt][3] = sA[bufc][k8 + tg + 4][m + g + 8];
            }
#pragma unroll
            for (int i = 0; i < 8; i++) {
                int n = wn * 64 + i * 8 + g;
                float b0 = sB[bufc][k8 + tg    ][n];
                float b1 = sB[bufc][k8 + tg + 4][n];
#pragma unroll
                for (int mt = 0; mt < 2; mt++)
                    mma_tf32(acc[mt][i], a[mt][0], a[mt][1], a[mt][2], a[mt][3],
                             b0, b1);
            }
        }
    }

    float* C = pfp + ((long)(seg * BH + bh)) * Ff * Ff;
#pragma unroll
    for (int mt = 0; mt < 2; mt++) {
        int m = wm * 32 + mt * 16;
#pragma unroll
        for (int i = 0; i < 8; i++) {
            int n = wn * 64 + i * 8 + 2 * tg;
            *(float2*)(C + (long)(m + g    ) * Ff + n) =
                make_float2(acc[mt][i][0], acc[mt][i][1]);
            *(float2*)(C + (long)(m + g + 8) * Ff + n) =
                make_float2(acc[mt][i][2], acc[mt][i][3]);
        }
    }
}

// ---------------------------------------------------------------------------
// sum 4 split-K partials, softmax, tf32-round -> pf. Block = one row.
// ---------------------------------------------------------------------------
__global__ void __launch_bounds__(128)
softmax_f_kernel(const float* __restrict__ pfp, float* __restrict__ pf)
{
    const int r = blockIdx.x;          // bh*128 + row
    const int bh = r >> 7, rr = r & 127;
    const int tid = threadIdx.x, lane = tid & 31, w = tid >> 5;
    __shared__ float red[4];
    __shared__ float bc;

    float v = 0.f;
#pragma unroll
    for (int seg = 0; seg < 4; seg++)
        v += pfp[(((long)(seg * BH + bh)) * Ff + rr) * Ff + tid];

    float m = v;
#pragma unroll
    for (int o = 16; o > 0; o >>= 1) m = fmaxf(m, __shfl_xor_sync(~0u, m, o));
    if (lane == 0) red[w] = m;
    __syncthreads();
    if (tid == 0) bc = fmaxf(fmaxf(red[0], red[1]), fmaxf(red[2], red[3]));
    __syncthreads();
    m = bc;
    float e = __expf(v - m);
    float s = e;
#pragma unroll
    for (int o = 16; o > 0; o >>= 1) s += __shfl_xor_sync(~0u, s, o);
    __syncthreads();
    if (lane == 0) red[w] = s;
    __syncthreads();
    if (tid == 0) bc = 1.f / (red[0] + red[1] + red[2] + red[3]);
    __syncthreads();
    pf[(long)r * Ff + tid] = to_tf32(e * bc);
}

// ---------------------------------------------------------------------------
// TF32 GEMM attn_f^T = v @ pf^T (2-stage pipelined). M=1024, N=128, K=128.
// ---------------------------------------------------------------------------
__global__ void __launch_bounds__(256, 2)
gemm_vp_kernel(const float* __restrict__ v, const float* __restrict__ pf,
               float* __restrict__ attn)
{
    extern __shared__ float dsm[];
    typedef float TileA[128][36];
    TileA* sA = (TileA*)dsm;
    TileA* sB = (TileA*)(dsm + 2 * 128 * 36);

    const int bh = blockIdx.y;
    const float* A = v  + (long)bh * Tt * Ff;
    const float* B = pf + (long)bh * Ff * Ff;
    const int m0 = blockIdx.x * 128;
    const int tid = threadIdx.x, warp = tid >> 5, lane = tid & 31;
    const int g = lane >> 2, tg = lane & 3;
    const int wm = warp >> 1, wn = warp & 1;

    float acc[2][8][4];
#pragma unroll
    for (int mt = 0; mt < 2; mt++)
#pragma unroll
        for (int i = 0; i < 8; i++)
#pragma unroll
            for (int j = 0; j < 4; j++) acc[mt][i][j] = 0.f;

    auto stage = [&](int kc, int bufi) {
#pragma unroll
        for (int it = 0; it < 4; it++) {
            int idx = tid + it * 256;
            int row = idx >> 3, q4 = (idx & 7) * 4;
            cp16(&sA[bufi][row][q4], A + (long)(m0 + row) * Ff + kc + q4, true);
            cp16(&sB[bufi][row][q4], B + (long)row * Ff + kc + q4, true);
        }
    };

    stage(0, 0);
    CP_COMMIT();

    for (int ci = 0; ci < 4; ci++) {
        const int bufc = ci & 1, bufn = (ci + 1) & 1;
        cp_wait<0>();
        __syncthreads();
        if (ci + 1 < 4) { stage((ci + 1) * 32, bufn); CP_COMMIT(); }

#pragma unroll
        for (int k8 = 0; k8 < 32; k8 += 8) {
            float a[2][4];
#pragma unroll
            for (int mt = 0; mt < 2; mt++) {
                int m = wm * 32 + mt * 16;
                a[mt][0] = sA[bufc][m + g    ][k8 + tg];
                a[mt][1] = sA[bufc][m + g + 8][k8 + tg];
                a[mt][2] = sA[bufc][m + g    ][k8 + tg + 4];
                a[mt][3] = sA[bufc][m + g + 8][k8 + tg + 4];
            }
#pragma unroll
            for (int i = 0; i < 8; i++) {
                int n = wn * 64 + i * 8 + g;
                float b0 = sB[bufc][n][k8 + tg];
                float b1 = sB[bufc][n][k8 + tg + 4];
#pragma unroll
                for (int mt = 0; mt < 2; mt++)
                    mma_tf32(acc[mt][i], a[mt][0], a[mt][1], a[mt][2], a[mt][3],
                             b0, b1);
            }
        }
    }

    const int b = bh >> 4, h = bh & 15;
    float* C = attn + ((long)(b * 32 + 16 + h)) * Tt * Ff;
#pragma unroll
    for (int mt = 0; mt < 2; mt++) {
        int m = m0 + wm * 32 + mt * 16;
#pragma unroll
        for (int i = 0; i < 8; i++) {
            int n = wn * 64 + i * 8 + 2 * tg;
            *(float2*)(C + (long)(m + g    ) * Ff + n) =
                make_float2(to_tf32(acc[mt][i][0]), to_tf32(acc[mt][i][1]));
            *(float2*)(C + (long)(m + g + 8) * Ff + n) =
                make_float2(to_tf32(acc[mt][i][2]), to_tf32(acc[mt][i][3]));
        }
    }
}

// ---------------------------------------------------------------------------
// Fused softmax (warp-per-head) + head-average. Block = (t, b), 512 threads.
// ---------------------------------------------------------------------------
__global__ void __launch_bounds__(512)
softmax_avg_kernel(float* __restrict__ aw, float* __restrict__ avg)
{
    extern __shared__ float se[];   // [16][1024]
    const int t = blockIdx.x, b = blockIdx.y;
    const int h = threadIdx.x >> 5, lane = threadIdx.x & 31;

    float4* row = reinterpret_cast<float4*>(
        aw + (((long)(b * Hh + h)) * Tt + t) * Tt);
    float4 v[8];
    float m = -1e30f;
#pragma unroll
    for (int j = 0; j < 8; j++) {
        v[j] = row[lane + 32 * j];
        m = fmaxf(m, fmaxf(fmaxf(v[j].x, v[j].y), fmaxf(v[j].z, v[j].w)));
    }
#pragma unroll
    for (int o = 16; o > 0; o >>= 1) m = fmaxf(m, __shfl_xor_sync(~0u, m, o));

    float s = 0.f;
#pragma unroll
    for (int j = 0; j < 8; j++) {
        v[j].x = __expf(v[j].x - m); v[j].y = __expf(v[j].y - m);
        v[j].z = __expf(v[j].z - m); v[j].w = __expf(v[j].w - m);
        s += v[j].x + v[j].y + v[j].z + v[j].w;
    }
#pragma unroll
    for (int o = 16; o > 0; o >>= 1) s += __shfl_xor_sync(~0u, s, o);
    const float inv = 1.f / s;

    float4* sh = reinterpret_cast<float4*>(se + h * 1024);
#pragma unroll
    for (int j = 0; j < 8; j++) {
        float4 e;
        e.x = to_tf32(v[j].x * inv); e.y = to_tf32(v[j].y * inv);
        e.z = to_tf32(v[j].z * inv); e.w = to_tf32(v[j].w * inv);
        row[lane + 32 * j] = e;
        sh[lane + 32 * j]  = e;
    }
    __syncthreads();

    float* op = avg + ((long)b * Tt + t) * Tt;
    for (int col = threadIdx.x; col < 1024; col += 512) {
        float a = 0.f;
#pragma unroll
        for (int hh = 0; hh < 16; hh++) a += se[hh * 1024 + col];
        op[col] = a * (1.f / 16.f);
    }
}

// ---------------------------------------------------------------------------
extern "C" void kernel_launch(void* const* d_in, const int* in_sizes, int n_in,
                              void* d_out, int out_size)
{
    const float* query = (const float*)d_in[0];
    const float* in_w  = (const float*)d_in[1];
    const float* in_b  = (const float*)d_in[2];
    const float* out_w = (const float*)d_in[3];
    const float* out_b = (const float*)d_in[4];

    float* out    = (float*)d_out;
    float* aw_avg = out + (long)Bsz * 128 * Tt * Ff;

    float *q, *k, *v, *aw, *attn, *pf, *pfp;
    cudaGetSymbolAddress((void**)&q,    g_q);
    cudaGetSymbolAddress((void**)&k,    g_k);
    cudaGetSymbolAddress((void**)&v,    g_v);
    cudaGetSymbolAddress((void**)&aw,   g_aw);
    cudaGetSymbolAddress((void**)&attn, g_attn);
    cudaGetSymbolAddress((void**)&pf,   g_pf);
    cudaGetSymbolAddress((void**)&pfp,  g_pfp);

    const int smem_conv_in  = (3 * 6 * 8 * 136 + 2 * 9 * 8 * 56) * 4;
    const int smem_conv_out = (3 * 6 * 8 * 136 + 2 * 9 * 8 * 40) * 4;
    const int smem_qk       = (2 * 128 * 68 * 2) * 4;                 // 139264
    const int smem_av       = (2 * (128 * 68 + 64 * 136)) * 4;        // 139264
    const int smem_qtk      = (2 * 32 * 132 * 2) * 4;
    const int smem_vp       = (2 * 128 * 36 * 2) * 4;
    const int smem_sm       = 16 * 1024 * 4;

    cudaFuncSetAttribute(conv_mma_kernel<128, 3, 0>,
        cudaFuncAttributeMaxDynamicSharedMemorySize, smem_conv_in);
    cudaFuncSetAttribute(conv_mma_kernel<32, 2, 1>,
        cudaFuncAttributeMaxDynamicSharedMemorySize, smem_conv_out);
    cudaFuncSetAttribute(gemm_qk_kernel,
        cudaFuncAttributeMaxDynamicSharedMemorySize, smem_qk);
    cudaFuncSetAttribute(gemm_av_kernel,
        cudaFuncAttributeMaxDynamicSharedMemorySize, smem_av);
    cudaFuncSetAttribute(gemm_qtk_kernel,
        cudaFuncAttributeMaxDynamicSharedMemorySize, smem_qtk);
    cudaFuncSetAttribute(gemm_vp_kernel,
        cudaFuncAttributeMaxDynamicSharedMemorySize, smem_vp);
    cudaFuncSetAttribute(softmax_avg_kernel,
        cudaFuncAttributeMaxDynamicSharedMemorySize, smem_sm);

    // 1. fused qkv conv — raw query (mma truncates x operand to tf32)
    conv_mma_kernel<128, 3, 0><<<dim3(256, 4, 1), 256, smem_conv_in>>>(
        query, in_w, in_b, q, k, v);

    // fork: freq path runs concurrently on g_s1
    cudaEventRecord(g_ev_fork, 0);
    cudaStreamWaitEvent(g_s1, g_ev_fork, 0);

    // s1: freq path (independent of time path)
    gemm_qtk_kernel<<<dim3(4, BH), 256, smem_qtk, g_s1>>>(q, k, pfp);
    softmax_f_kernel<<<BH * Ff, 128, 0, g_s1>>>(pfp, pf);
    gemm_vp_kernel<<<dim3(8, BH), 256, smem_vp, g_s1>>>(v, pf, attn);
    cudaEventRecord(g_ev_join, g_s1);

    // s0: time path
    gemm_qk_kernel<<<dim3(8, 8, BH), 256, smem_qk>>>(q, k, aw);
    softmax_avg_kernel<<<dim3(1024, Bsz), 512, smem_sm>>>(aw, aw_avg);
    gemm_av_kernel<<<dim3(8, BH), 256, smem_av>>>(aw, v, attn);

    // join freq path before the output conv
    cudaStreamWaitEvent(0, g_ev_join, 0);

    // 8. output conv (3-stage x pipeline)
    conv_mma_kernel<32, 2, 1><<<dim3(256, 4, 4), 256, smem_conv_out>>>(
        attn, out_w, out_b, out, nullptr, nullptr);
}

// round 15
// speedup vs baseline: 1.1100x; 1.0924x over previous
#include <cuda_runtime.h>
#include <cuda_bf16.h>
#include <cstdint>

#define Bsz 4
#define Hh  16
#define Tt  1024
#define Ff  128
#define BH  64

static const float SCALING = 0.08838834764831845f; // 128^-0.5

__device__ float g_q   [(long)BH * Tt * Ff];
__device__ float g_k   [(long)BH * Tt * Ff];
__device__ float g_v   [(long)BH * Tt * Ff];
__device__ float g_aw  [(long)BH * Tt * Tt];
__device__ __nv_bfloat16 g_awh[(long)BH * Tt * Tt];   // bf16 softmax weights
__device__ __nv_bfloat16 g_vth[(long)BH * Ff * Tt];   // bf16 v^T [bh][f][t]
__device__ float g_attn[(long)Bsz * 32 * Tt * Ff];
__device__ float g_pf  [(long)BH * Ff * Ff];
__device__ float g_pfp [(long)4 * BH * Ff * Ff];

// streams/events created once at load time (outside graph capture)
static cudaStream_t g_s1;
static cudaEvent_t  g_ev_fork, g_ev_join, g_ev_vt;
static struct StreamInit {
    StreamInit() {
        cudaStreamCreateWithFlags(&g_s1, cudaStreamNonBlocking);
        cudaEventCreateWithFlags(&g_ev_fork, cudaEventDisableTiming);
        cudaEventCreateWithFlags(&g_ev_join, cudaEventDisableTiming);
        cudaEventCreateWithFlags(&g_ev_vt,   cudaEventDisableTiming);
    }
} g_stream_init;

__device__ __forceinline__ float to_tf32(float x) {
    uint32_t u;
    asm("cvt.rna.tf32.f32 %0, %1;" : "=r"(u) : "f"(x));
    return __uint_as_float(u);
}
__device__ __forceinline__ void mma_tf32(float* d, float a0, float a1,
                                         float a2, float a3, float b0, float b1)
{
    asm volatile(
        "mma.sync.aligned.m16n8k8.row.col.f32.tf32.tf32.f32 "
        "{%0,%1,%2,%3}, {%4,%5,%6,%7}, {%8,%9}, {%0,%1,%2,%3};\n"
        : "+f"(d[0]), "+f"(d[1]), "+f"(d[2]), "+f"(d[3])
        : "r"(__float_as_uint(a0)), "r"(__float_as_uint(a1)),
          "r"(__float_as_uint(a2)), "r"(__float_as_uint(a3)),
          "r"(__float_as_uint(b0)), "r"(__float_as_uint(b1)));
}
__device__ __forceinline__ void mma_bf16(float* d, uint32_t a0, uint32_t a1,
                                         uint32_t a2, uint32_t a3,
                                         uint32_t b0, uint32_t b1)
{
    asm volatile(
        "mma.sync.aligned.m16n8k16.row.col.f32.bf16.bf16.f32 "
        "{%0,%1,%2,%3}, {%4,%5,%6,%7}, {%8,%9}, {%0,%1,%2,%3};\n"
        : "+f"(d[0]), "+f"(d[1]), "+f"(d[2]), "+f"(d[3])
        : "r"(a0), "r"(a1), "r"(a2), "r"(a3), "r"(b0), "r"(b1));
}

__device__ __forceinline__ void cp16(void* smem, const void* gmem, bool pred) {
    uint32_t s = (uint32_t)__cvta_generic_to_shared(smem);
    asm volatile("cp.async.ca.shared.global [%0], [%1], 16, %2;\n"
                 :: "r"(s), "l"(gmem), "r"(pred ? 16 : 0));
}
#define CP_COMMIT() asm volatile("cp.async.commit_group;\n")
template<int N>
__device__ __forceinline__ void cp_wait() {
    asm volatile("cp.async.wait_group %0;\n" :: "n"(N));
}

// ---------------------------------------------------------------------------
// TF32 implicit-GEMM 3x3 conv (pad 1), 3-stage cp.async (R8 proven).
// ---------------------------------------------------------------------------
template<int CIN, int MT, int EPI>
__global__ void __launch_bounds__(256)
conv_mma_kernel(const float* __restrict__ in, const float* __restrict__ w,
                const float* __restrict__ bias,
                float* __restrict__ o0, float* __restrict__ o1,
                float* __restrict__ o2)
{
    constexpr int WPAD = MT * 16 + 8;
    constexpr int NC   = CIN / 8;
    constexpr int NW   = MT * 16 * 72;
    constexpr int WREG = (NW + 255) / 256;

    extern __shared__ float dsm[];
    typedef float XBuf[6][8][136];
    typedef float WBuf[9][8][WPAD];
    XBuf* s_x = (XBuf*)dsm;                        // [3]
    WBuf* s_w = (WBuf*)(dsm + 3 * 6 * 8 * 136);    // [2]

    const int tid = threadIdx.x;
    const int warp = tid >> 5, lane = tid & 31;
    const int g = lane >> 2, tg = lane & 3;
    const int tt_w = warp >> 1;
    const int f0_w = (warp & 1) * 64;
    const int t0 = blockIdx.x * 4;
    const int b  = blockIdx.y;
    const int mg = blockIdx.z;

    for (int idx = tid; idx < 288; idx += 256) {
        int bufi = idx / 96, rem = idx % 96;
        int r = rem / 16, c = (rem >> 1) & 7, col = (rem & 1) ? 132 : 3;
        s_x[bufi][r][c][col] = 0.f;
    }

    float acc[MT][8][4];
#pragma unroll
    for (int mt = 0; mt < MT; mt++)
#pragma unroll
        for (int i = 0; i < 8; i++)
#pragma unroll
            for (int j = 0; j < 4; j++) acc[mt][i][j] = 0.f;

    auto stage_x = [&](int cb, int bufi) {
#pragma unroll
        for (int it = 0; it < 6; it++) {
            int idx = tid + it * 256;
            int v = idx & 31, rc = idx >> 5;
            int r = rc >> 3, c = rc & 7;
            int trow = t0 - 1 + r;
            bool ok = (unsigned)trow < 1024u;
            const float* src = in +
                (((long)(b * CIN + cb + c)) * 1024 + (ok ? trow : 0)) * 128 + 4 * v;
            cp16(&s_x[bufi][r][c][4 + 4 * v], src, ok);
        }
    };

    for (int idx = tid; idx < NW; idx += 256) {
        int co = idx / 72, rem = idx % 72, c = rem / 9, tap = rem % 9;
        s_w[0][tap][c][co] =
            to_tf32(w[((long)(mg * MT * 16 + co) * CIN + c) * 9 + tap]);
    }
    stage_x(0, 0);
    CP_COMMIT();
    stage_x(8, 1);
    CP_COMMIT();

    for (int ci = 0; ci < NC; ci++) {
        const int bufc = ci % 3;
        const int wbc = ci & 1, wbn = (ci + 1) & 1;

        float wreg[WREG];
        if (ci + 1 < NC) {
#pragma unroll
            for (int it = 0; it < WREG; it++) {
                int idx = tid + it * 256;
                if (idx < NW) {
                    int co = idx / 72, rem = idx % 72, c = rem / 9, tap = rem % 9;
                    wreg[it] = w[((long)(mg * MT * 16 + co) * CIN
                                  + (ci + 1) * 8 + c) * 9 + tap];
                }
            }
        }

        if (ci + 1 < NC) cp_wait<1>(); else cp_wait<0>();
        __syncthreads();

        if (ci + 2 < NC) {
            stage_x((ci + 2) * 8, (ci + 2) % 3);
            CP_COMMIT();
        }
        if (ci + 1 < NC) {
#pragma unroll
            for (int it = 0; it < WREG; it++) {
                int idx = tid + it * 256;
                if (idx < NW) {
                    int co = idx / 72, rem = idx % 72, c = rem / 9, tap = rem % 9;
                    s_w[wbn][tap][c][co] = to_tf32(wreg[it]);
                }
            }
        }

#pragma unroll
        for (int tap = 0; tap < 9; tap++) {
            const int dt = tap / 3, df = tap % 3;
            float a[MT][4];
#pragma unroll
            for (int mt = 0; mt < MT; mt++) {
                a[mt][0] = s_w[wbc][tap][tg    ][mt * 16 + g];
                a[mt][1] = s_w[wbc][tap][tg    ][mt * 16 + g + 8];
                a[mt][2] = s_w[wbc][tap][tg + 4][mt * 16 + g];
                a[mt][3] = s_w[wbc][tap][tg + 4][mt * 16 + g + 8];
            }
            const float* xr = &s_x[bufc][tt_w + dt][0][0];
#pragma unroll
            for (int i = 0; i < 8; i++) {
                int col = 3 + f0_w + i * 8 + g + df;
                float b0 = xr[tg * 136 + col];
                float b1 = xr[(tg + 4) * 136 + col];
#pragma unroll
                for (int mt = 0; mt < MT; mt++)
                    mma_tf32(acc[mt][i], a[mt][0], a[mt][1], a[mt][2], a[mt][3],
                             b0, b1);
            }
        }
    }

    const int t = t0 + tt_w;
#pragma unroll
    for (int mt = 0; mt < MT; mt++) {
        if (EPI == 0) {
            float bv0 = bias[mt * 16 + g], bv1 = bias[mt * 16 + g + 8];
            const float sc = (mt == 0) ? SCALING : 1.f;
            float* dst = (mt == 0) ? o0 : (mt == 1) ? o1 : o2;
            long base0 = (((long)(b * Hh + g    )) * Tt + t) * Ff;
            long base1 = (((long)(b * Hh + g + 8)) * Tt + t) * Ff;
#pragma unroll
            for (int i = 0; i < 8; i++) {
                int f = f0_w + i * 8 + 2 * tg;
                float2 r0, r1;
                r0.x = to_tf32(fmaxf((acc[mt][i][0] + bv0) * sc, 0.f));
                r0.y = to_tf32(fmaxf((acc[mt][i][1] + bv0) * sc, 0.f));
                r1.x = to_tf32(fmaxf((acc[mt][i][2] + bv1) * sc, 0.f));
                r1.y = to_tf32(fmaxf((acc[mt][i][3] + bv1) * sc, 0.f));
                *(float2*)(dst + base0 + f) = r0;
                *(float2*)(dst + base1 + f) = r1;
            }
        } else {
            int co0 = mg * MT * 16 + mt * 16 + g, co1 = co0 + 8;
            float bv0 = bias[co0], bv1 = bias[co1];
            long base0 = (((long)(b * 128 + co0)) * Tt + t) * Ff;
            long base1 = (((long)(b * 128 + co1)) * Tt + t) * Ff;
#pragma unroll
            for (int i = 0; i < 8; i++) {
                int f = f0_w + i * 8 + 2 * tg;
                float2 r0, r1;
                r0.x = fmaxf(acc[mt][i][0] + bv0, 0.f);
                r0.y = fmaxf(acc[mt][i][1] + bv0, 0.f);
                r1.x = fmaxf(acc[mt][i][2] + bv1, 0.f);
                r1.y = fmaxf(acc[mt][i][3] + bv1, 0.f);
                *(float2*)(o0 + base0 + f) = r0;
                *(float2*)(o0 + base1 + f) = r1;
            }
        }
    }
}

// ---------------------------------------------------------------------------
// TF32 GEMM scores = q @ k^T. BK=64, double-buffered, 256 thr (R11 best).
// ---------------------------------------------------------------------------
__global__ void __launch_bounds__(256)
gemm_qk_kernel(const float* __restrict__ q, const float* __restrict__ kmat,
               float* __restrict__ aw)
{
    extern __shared__ float dsm[];
    typedef float TileA[128][68];
    TileA* sA = (TileA*)dsm;                    // [2]
    TileA* sB = (TileA*)(dsm + 2 * 128 * 68);   // [2]

    const int bh = blockIdx.z;
    const float* A = q    + (long)bh * Tt * Ff;
    const float* B = kmat + (long)bh * Tt * Ff;
    const int m0 = blockIdx.y * 128, n0 = blockIdx.x * 128;
    const int tid = threadIdx.x, warp = tid >> 5, lane = tid & 31;
    const int g = lane >> 2, tg = lane & 3;
    const int wm = warp >> 1, wn = warp & 1;

    float acc[2][8][4];
#pragma unroll
    for (int mt = 0; mt < 2; mt++)
#pragma unroll
        for (int i = 0; i < 8; i++)
#pragma unroll
            for (int j = 0; j < 4; j++) acc[mt][i][j] = 0.f;

    auto stage = [&](int kc, int bufi) {
#pragma unroll
        for (int it = 0; it < 8; it++) {
            int idx = tid + it * 256;
            int row = idx >> 4, q4 = (idx & 15) * 4;
            cp16(&sA[bufi][row][q4], A + (long)(m0 + row) * Ff + kc + q4, true);
            cp16(&sB[bufi][row][q4], B + (long)(n0 + row) * Ff + kc + q4, true);
        }
    };

    stage(0, 0);
    CP_COMMIT();

    for (int ci = 0; ci < 2; ci++) {
        const int bufc = ci & 1, bufn = (ci + 1) & 1;
        cp_wait<0>();
        __syncthreads();
        if (ci + 1 < 2) { stage(64, bufn); CP_COMMIT(); }

#pragma unroll
        for (int k8 = 0; k8 < 64; k8 += 8) {
            float a[2][4];
#pragma unroll
            for (int mt = 0; mt < 2; mt++) {
                int m = wm * 32 + mt * 16;
                a[mt][0] = sA[bufc][m + g    ][k8 + tg];
                a[mt][1] = sA[bufc][m + g + 8][k8 + tg];
                a[mt][2] = sA[bufc][m + g    ][k8 + tg + 4];
                a[mt][3] = sA[bufc][m + g + 8][k8 + tg + 4];
            }
#pragma unroll
            for (int i = 0; i < 8; i++) {
                int n = wn * 64 + i * 8 + g;
                float b0 = sB[bufc][n][k8 + tg];
                float b1 = sB[bufc][n][k8 + tg + 4];
#pragma unroll
                for (int mt = 0; mt < 2; mt++)
                    mma_tf32(acc[mt][i], a[mt][0], a[mt][1], a[mt][2], a[mt][3],
                             b0, b1);
            }
        }
    }

    float* C = aw + (long)bh * Tt * Tt;
#pragma unroll
    for (int mt = 0; mt < 2; mt++) {
        int m = m0 + wm * 32 + mt * 16;
#pragma unroll
        for (int i = 0; i < 8; i++) {
            int n = n0 + wn * 64 + i * 8 + 2 * tg;
            *(float2*)(C + (long)(m + g    ) * Tt + n) =
                make_float2(acc[mt][i][0], acc[mt][i][1]);
            *(float2*)(C + (long)(m + g + 8) * Tt + n) =
                make_float2(acc[mt][i][2], acc[mt][i][3]);
        }
    }
}

// ---------------------------------------------------------------------------
// BF16 GEMM attn_t = awh @ vth^T. m16n8k16, BK=128 double-buffered.
// A = awh[bh] [m=t][k=s] bf16, B = vth[bh] [n=f][k=t] bf16, both k-contig.
// ---------------------------------------------------------------------------
__global__ void __launch_bounds__(256)
gemm_av_kernel(const __nv_bfloat16* __restrict__ awh,
               const __nv_bfloat16* __restrict__ vth,
               float* __restrict__ attn)
{
    extern __shared__ __nv_bfloat16 smh[];
    constexpr int RS  = 136;               // bf16 row stride (272B, 17x16B)
    constexpr int STG = 2 * 128 * RS;      // one stage: A + B tiles
    const int bh = blockIdx.y;
    const __nv_bfloat16* A = awh + (long)bh * Tt * Tt;
    const __nv_bfloat16* B = vth + (long)bh * Ff * Tt;
    const int m0 = blockIdx.x * 128;
    const int tid = threadIdx.x, warp = tid >> 5, lane = tid & 31;
    const int g = lane >> 2, tg = lane & 3;
    const int wm = warp >> 1, wn = warp & 1;

    float acc[2][8][4];
#pragma unroll
    for (int mt = 0; mt < 2; mt++)
#pragma unroll
        for (int i = 0; i < 8; i++)
#pragma unroll
            for (int j = 0; j < 4; j++) acc[mt][i][j] = 0.f;

    auto stage = [&](int kc, int bufi) {
        __nv_bfloat16* pA = smh + bufi * STG;
        __nv_bfloat16* pB = pA + 128 * RS;
#pragma unroll
        for (int it = 0; it < 8; it++) {
            int idx = tid + it * 256;
            int row = idx >> 4, seg = idx & 15;   // 16 x 16B per 256B row
            cp16(&pA[row * RS + seg * 8],
                 A + (long)(m0 + row) * Tt + kc + seg * 8, true);
            cp16(&pB[row * RS + seg * 8],
                 B + (long)row * Tt + kc + seg * 8, true);
        }
    };

    stage(0, 0);
    CP_COMMIT();

    for (int ci = 0; ci < 8; ci++) {
        const int bufc = ci & 1;
        const __nv_bfloat16* sA = smh + bufc * STG;
        const __nv_bfloat16* sB = sA + 128 * RS;

        cp_wait<0>();
        __syncthreads();
        if (ci + 1 < 8) { stage((ci + 1) * 128, bufc ^ 1); CP_COMMIT(); }

#pragma unroll
        for (int k16 = 0; k16 < 128; k16 += 16) {
            uint32_t a[2][4];
#pragma unroll
            for (int mt = 0; mt < 2; mt++) {
                int m = wm * 32 + mt * 16;
                a[mt][0] = *(const uint32_t*)&sA[(m + g    ) * RS + k16 + 2 * tg];
                a[mt][1] = *(const uint32_t*)&sA[(m + g + 8) * RS + k16 + 2 * tg];
                a[mt][2] = *(const uint32_t*)&sA[(m + g    ) * RS + k16 + 2 * tg + 8];
                a[mt][3] = *(const uint32_t*)&sA[(m + g + 8) * RS + k16 + 2 * tg + 8];
            }
#pragma unroll
            for (int i = 0; i < 8; i++) {
                int n = wn * 64 + i * 8 + g;
                uint32_t b0 = *(const uint32_t*)&sB[n * RS + k16 + 2 * tg];
                uint32_t b1 = *(const uint32_t*)&sB[n * RS + k16 + 2 * tg + 8];
#pragma unroll
                for (int mt = 0; mt < 2; mt++)
                    mma_bf16(acc[mt][i], a[mt][0], a[mt][1], a[mt][2], a[mt][3],
                             b0, b1);
            }
        }
    }

    const int b = bh >> 4, h = bh & 15;
    float* C = attn + ((long)(b * 32 + h)) * Tt * Ff;
#pragma unroll
    for (int mt = 0; mt < 2; mt++) {
        int m = m0 + wm * 32 + mt * 16;
#pragma unroll
        for (int i = 0; i < 8; i++) {
            int n = wn * 64 + i * 8 + 2 * tg;
            *(float2*)(C + (long)(m + g    ) * Ff + n) =
                make_float2(to_tf32(acc[mt][i][0]), to_tf32(acc[mt][i][1]));
            *(float2*)(C + (long)(m + g + 8) * Ff + n) =
                make_float2(to_tf32(acc[mt][i][2]), to_tf32(acc[mt][i][3]));
        }
    }
}

// ---------------------------------------------------------------------------
// v transpose to bf16: vth[bh][f][t] = bf16(v[bh][t][f])
// ---------------------------------------------------------------------------
__global__ void __launch_bounds__(256)
transpose_v_kernel(const float* __restrict__ v, __nv_bfloat16* __restrict__ vt)
{
    __shared__ float ts[32][33];
    const int bh = blockIdx.z;
    const int t0 = blockIdx.x * 32, f0 = blockIdx.y * 32;
    const float* src = v + (long)bh * Tt * Ff;
    __nv_bfloat16* dst = vt + (long)bh * Ff * Tt;
    const int tx = threadIdx.x & 31, ty = threadIdx.x >> 5;
#pragma unroll
    for (int i = 0; i < 32; i += 8)
        ts[ty + i][tx] = src[(long)(t0 + ty + i) * Ff + f0 + tx];
    __syncthreads();
#pragma unroll
    for (int i = 0; i < 32; i += 8)
        dst[(long)(f0 + ty + i) * Tt + t0 + tx] =
            __float2bfloat16_rn(ts[tx][ty + i]);
}

// ---------------------------------------------------------------------------
// TF32 GEMM pf partials = q^T @ k (split-K x4, 2-stage). (R8 proven)
// ---------------------------------------------------------------------------
__global__ void __launch_bounds__(256, 2)
gemm_qtk_kernel(const float* __restrict__ q, const float* __restrict__ kmat,
                float* __restrict__ pfp)
{
    extern __shared__ float dsm[];
    typedef float Tile[32][132];
    Tile* sA = (Tile*)dsm;
    Tile* sB = (Tile*)(dsm + 2 * 32 * 132);

    const int seg = blockIdx.x, bh = blockIdx.y;
    const float* A = q    + (long)bh * Tt * Ff;
    const float* B = kmat + (long)bh * Tt * Ff;
    const int k0 = seg * 256;
    const int tid = threadIdx.x, warp = tid >> 5, lane = tid & 31;
    const int g = lane >> 2, tg = lane & 3;
    const int wm = warp >> 1, wn = warp & 1;

    float acc[2][8][4];
#pragma unroll
    for (int mt = 0; mt < 2; mt++)
#pragma unroll
        for (int i = 0; i < 8; i++)
#pragma unroll
            for (int j = 0; j < 4; j++) acc[mt][i][j] = 0.f;

    auto stage = [&](int kc, int bufi) {
#pragma unroll
        for (int it = 0; it < 4; it++) {
            int idx = tid + it * 256;
            int kk = idx >> 5, c4 = (idx & 31) * 4;
            cp16(&sA[bufi][kk][c4], A + (long)(k0 + kc + kk) * Ff + c4, true);
            cp16(&sB[bufi][kk][c4], B + (long)(k0 + kc + kk) * Ff + c4, true);
        }
    };

    stage(0, 0);
    CP_COMMIT();

    for (int ci = 0; ci < 8; ci++) {
        const int bufc = ci & 1, bufn = (ci + 1) & 1;
        cp_wait<0>();
        __syncthreads();
        if (ci + 1 < 8) { stage((ci + 1) * 32, bufn); CP_COMMIT(); }

#pragma unroll
        for (int k8 = 0; k8 < 32; k8 += 8) {
            float a[2][4];
#pragma unroll
            for (int mt = 0; mt < 2; mt++) {
                int m = wm * 32 + mt * 16;
                a[mt][0] = sA[bufc][k8 + tg    ][m + g];
                a[mt][1] = sA[bufc][k8 + tg    ][m + g + 8];
                a[mt][2] = sA[bufc][k8 + tg + 4][m + g];
                a[mt][3] = sA[bufc][k8 + tg + 4][m + g + 8];
            }
#pragma unroll
            for (int i = 0; i < 8; i++) {
                int n = wn * 64 + i * 8 + g;
                float b0 = sB[bufc][k8 + tg    ][n];
                float b1 = sB[bufc][k8 + tg + 4][n];
#pragma unroll
                for (int mt = 0; mt < 2; mt++)
                    mma_tf32(acc[mt][i], a[mt][0], a[mt][1], a[mt][2], a[mt][3],
                             b0, b1);
            }
        }
    }

    float* C = pfp + ((long)(seg * BH + bh)) * Ff * Ff;
#pragma unroll
    for (int mt = 0; mt < 2; mt++) {
        int m = wm * 32 + mt * 16;
#pragma unroll
        for (int i = 0; i < 8; i++) {
            int n = wn * 64 + i * 8 + 2 * tg;
            *(float2*)(C + (long)(m + g    ) * Ff + n) =
                make_float2(acc[mt][i][0], acc[mt][i][1]);
            *(float2*)(C + (long)(m + g + 8) * Ff + n) =
                make_float2(acc[mt][i][2], acc[mt][i][3]);
        }
    }
}

// ---------------------------------------------------------------------------
__global__ void __launch_bounds__(128)
softmax_f_kernel(const float* __restrict__ pfp, float* __restrict__ pf)
{
    const int r = blockIdx.x;
    const int bh = r >> 7, rr = r & 127;
    const int tid = threadIdx.x, lane = tid & 31, w = tid >> 5;
    __shared__ float red[4];
    __shared__ float bc;

    float v = 0.f;
#pragma unroll
    for (int seg = 0; seg < 4; seg++)
        v += pfp[(((long)(seg * BH + bh)) * Ff + rr) * Ff + tid];

    float m = v;
#pragma unroll
    for (int o = 16; o > 0; o >>= 1) m = fmaxf(m, __shfl_xor_sync(~0u, m, o));
    if (lane == 0) red[w] = m;
    __syncthreads();
    if (tid == 0) bc = fmaxf(fmaxf(red[0], red[1]), fmaxf(red[2], red[3]));
    __syncthreads();
    m = bc;
    float e = __expf(v - m);
    float s = e;
#pragma unroll
    for (int o = 16; o > 0; o >>= 1) s += __shfl_xor_sync(~0u, s, o);
    __syncthreads();
    if (lane == 0) red[w] = s;
    __syncthreads();
    if (tid == 0) bc = 1.f / (red[0] + red[1] + red[2] + red[3]);
    __syncthreads();
    pf[(long)r * Ff + tid] = to_tf32(e * bc);
}

// ---------------------------------------------------------------------------
// TF32 GEMM attn_f^T = v @ pf^T (2-stage). M=1024, N=128, K=128.
// ---------------------------------------------------------------------------
__global__ void __launch_bounds__(256, 2)
gemm_vp_kernel(const float* __restrict__ v, const float* __restrict__ pf,
               float* __restrict__ attn)
{
    extern __shared__ float dsm[];
    typedef float TileA[128][36];
    TileA* sA = (TileA*)dsm;
    TileA* sB = (TileA*)(dsm + 2 * 128 * 36);

    const int bh = blockIdx.y;
    const float* A = v  + (long)bh * Tt * Ff;
    const float* B = pf + (long)bh * Ff * Ff;
    const int m0 = blockIdx.x * 128;
    const int tid = threadIdx.x, warp = tid >> 5, lane = tid & 31;
    const int g = lane >> 2, tg = lane & 3;
    const int wm = warp >> 1, wn = warp & 1;

    float acc[2][8][4];
#pragma unroll
    for (int mt = 0; mt < 2; mt++)
#pragma unroll
        for (int i = 0; i < 8; i++)
#pragma unroll
            for (int j = 0; j < 4; j++) acc[mt][i][j] = 0.f;

    auto stage = [&](int kc, int bufi) {
#pragma unroll
        for (int it = 0; it < 4; it++) {
            int idx = tid + it * 256;
            int row = idx >> 3, q4 = (idx & 7) * 4;
            cp16(&sA[bufi][row][q4], A + (long)(m0 + row) * Ff + kc + q4, true);
            cp16(&sB[bufi][row][q4], B + (long)row * Ff + kc + q4, true);
        }
    };

    stage(0, 0);
    CP_COMMIT();

    for (int ci = 0; ci < 4; ci++) {
        const int bufc = ci & 1, bufn = (ci + 1) & 1;
        cp_wait<0>();
        __syncthreads();
        if (ci + 1 < 4) { stage((ci + 1) * 32, bufn); CP_COMMIT(); }

#pragma unroll
        for (int k8 = 0; k8 < 32; k8 += 8) {
            float a[2][4];
#pragma unroll
            for (int mt = 0; mt < 2; mt++) {
                int m = wm * 32 + mt * 16;
                a[mt][0] = sA[bufc][m + g    ][k8 + tg];
                a[mt][1] = sA[bufc][m + g + 8][k8 + tg];
                a[mt][2] = sA[bufc][m + g    ][k8 + tg + 4];
                a[mt][3] = sA[bufc][m + g + 8][k8 + tg + 4];
            }
#pragma unroll
            for (int i = 0; i < 8; i++) {
                int n = wn * 64 + i * 8 + g;
                float b0 = sB[bufc][n][k8 + tg];
                float b1 = sB[bufc][n][k8 + tg + 4];
#pragma unroll
                for (int mt = 0; mt < 2; mt++)
                    mma_tf32(acc[mt][i], a[mt][0], a[mt][1], a[mt][2], a[mt][3],
                             b0, b1);
            }
        }
    }

    const int b = bh >> 4, h = bh & 15;
    float* C = attn + ((long)(b * 32 + 16 + h)) * Tt * Ff;
#pragma unroll
    for (int mt = 0; mt < 2; mt++) {
        int m = m0 + wm * 32 + mt * 16;
#pragma unroll
        for (int i = 0; i < 8; i++) {
            int n = wn * 64 + i * 8 + 2 * tg;
            *(float2*)(C + (long)(m + g    ) * Ff + n) =
                make_float2(to_tf32(acc[mt][i][0]), to_tf32(acc[mt][i][1]));
            *(float2*)(C + (long)(m + g + 8) * Ff + n) =
                make_float2(to_tf32(acc[mt][i][2]), to_tf32(acc[mt][i][3]));
        }
    }
}

// ---------------------------------------------------------------------------
// Fused softmax (warp-per-head) + head-average. Writes bf16 weights to awh
// (fp32 aw is not written back — nothing reads it after this kernel).
// ---------------------------------------------------------------------------
__global__ void __launch_bounds__(512)
softmax_avg_kernel(const float* __restrict__ aw, __nv_bfloat16* __restrict__ awh,
                   float* __restrict__ avg)
{
    extern __shared__ float se[];   // [16][1024]
    const int t = blockIdx.x, b = blockIdx.y;
    const int h = threadIdx.x >> 5, lane = threadIdx.x & 31;

    const float4* row = reinterpret_cast<const float4*>(
        aw + (((long)(b * Hh + h)) * Tt + t) * Tt);
    __nv_bfloat162* rowh = reinterpret_cast<__nv_bfloat162*>(
        awh + (((long)(b * Hh + h)) * Tt + t) * Tt);
    float4 v[8];
    float m = -1e30f;
#pragma unroll
    for (int j = 0; j < 8; j++) {
        v[j] = row[lane + 32 * j];
        m = fmaxf(m, fmaxf(fmaxf(v[j].x, v[j].y), fmaxf(v[j].z, v[j].w)));
    }
#pragma unroll
    for (int o = 16; o > 0; o >>= 1) m = fmaxf(m, __shfl_xor_sync(~0u, m, o));

    float s = 0.f;
#pragma unroll
    for (int j = 0; j < 8; j++) {
        v[j].x = __expf(v[j].x - m); v[j].y = __expf(v[j].y - m);
        v[j].z = __expf(v[j].z - m); v[j].w = __expf(v[j].w - m);
        s += v[j].x + v[j].y + v[j].z + v[j].w;
    }
#pragma unroll
    for (int o = 16; o > 0; o >>= 1) s += __shfl_xor_sync(~0u, s, o);
    const float inv = 1.f / s;

    float4* sh = reinterpret_cast<float4*>(se + h * 1024);
#pragma unroll
    for (int j = 0; j < 8; j++) {
        float4 e;
        e.x = v[j].x * inv; e.y = v[j].y * inv;
        e.z = v[j].z * inv; e.w = v[j].w * inv;
        rowh[(lane + 32 * j) * 2    ] = __floats2bfloat162_rn(e.x, e.y);
        rowh[(lane + 32 * j) * 2 + 1] = __floats2bfloat162_rn(e.z, e.w);
        sh[lane + 32 * j] = e;
    }
    __syncthreads();

    float* op = avg + ((long)b * Tt + t) * Tt;
    for (int col = threadIdx.x; col < 1024; col += 512) {
        float a = 0.f;
#pragma unroll
        for (int hh = 0; hh < 16; hh++) a += se[hh * 1024 + col];
        op[col] = a * (1.f / 16.f);
    }
}

// ---------------------------------------------------------------------------
extern "C" void kernel_launch(void* const* d_in, const int* in_sizes, int n_in,
                              void* d_out, int out_size)
{
    const float* query = (const float*)d_in[0];
    const float* in_w  = (const float*)d_in[1];
    const float* in_b  = (const float*)d_in[2];
    const float* out_w = (const float*)d_in[3];
    const float* out_b = (const float*)d_in[4];

    float* out    = (float*)d_out;
    float* aw_avg = out + (long)Bsz * 128 * Tt * Ff;

    float *q, *k, *v, *aw, *attn, *pf, *pfp;
    __nv_bfloat16 *awh, *vth;
    cudaGetSymbolAddress((void**)&q,    g_q);
    cudaGetSymbolAddress((void**)&k,    g_k);
    cudaGetSymbolAddress((void**)&v,    g_v);
    cudaGetSymbolAddress((void**)&aw,   g_aw);
    cudaGetSymbolAddress((void**)&awh,  g_awh);
    cudaGetSymbolAddress((void**)&vth,  g_vth);
    cudaGetSymbolAddress((void**)&attn, g_attn);
    cudaGetSymbolAddress((void**)&pf,   g_pf);
    cudaGetSymbolAddress((void**)&pfp,  g_pfp);

    const int smem_conv_in  = (3 * 6 * 8 * 136 + 2 * 9 * 8 * 56) * 4;
    const int smem_conv_out = (3 * 6 * 8 * 136 + 2 * 9 * 8 * 40) * 4;
    const int smem_qk       = (2 * 128 * 68 * 2) * 4;                 // 139264
    const int smem_av       = (2 * 2 * 128 * 136) * 2;                // 139264 (bf16)
    const int smem_qtk      = (2 * 32 * 132 * 2) * 4;
    const int smem_vp       = (2 * 128 * 36 * 2) * 4;
    const int smem_sm       = 16 * 1024 * 4;

    cudaFuncSetAttribute(conv_mma_kernel<128, 3, 0>,
        cudaFuncAttributeMaxDynamicSharedMemorySize, smem_conv_in);
    cudaFuncSetAttribute(conv_mma_kernel<32, 2, 1>,
        cudaFuncAttributeMaxDynamicSharedMemorySize, smem_conv_out);
    cudaFuncSetAttribute(gemm_qk_kernel,
        cudaFuncAttributeMaxDynamicSharedMemorySize, smem_qk);
    cudaFuncSetAttribute(gemm_av_kernel,
        cudaFuncAttributeMaxDynamicSharedMemorySize, smem_av);
    cudaFuncSetAttribute(gemm_qtk_kernel,
        cudaFuncAttributeMaxDynamicSharedMemorySize, smem_qtk);
    cudaFuncSetAttribute(gemm_vp_kernel,
        cudaFuncAttributeMaxDynamicSharedMemorySize, smem_vp);
    cudaFuncSetAttribute(softmax_avg_kernel,
        cudaFuncAttributeMaxDynamicSharedMemorySize, smem_sm);

    // 1. fused qkv conv
    conv_mma_kernel<128, 3, 0><<<dim3(256, 4, 1), 256, smem_conv_in>>>(
        query, in_w, in_b, q, k, v);

    // fork: freq path + v transpose run concurrently on g_s1
    cudaEventRecord(g_ev_fork, 0);
    cudaStreamWaitEvent(g_s1, g_ev_fork, 0);

    // s1: v transpose (needed by av on s0), then freq path
    transpose_v_kernel<<<dim3(32, 4, BH), 256, 0, g_s1>>>(v, vth);
    cudaEventRecord(g_ev_vt, g_s1);
    gemm_qtk_kernel<<<dim3(4, BH), 256, smem_qtk, g_s1>>>(q, k, pfp);
    softmax_f_kernel<<<BH * Ff, 128, 0, g_s1>>>(pfp, pf);
    gemm_vp_kernel<<<dim3(8, BH), 256, smem_vp, g_s1>>>(v, pf, attn);
    cudaEventRecord(g_ev_join, g_s1);

    // s0: time path
    gemm_qk_kernel<<<dim3(8, 8, BH), 256, smem_qk>>>(q, k, aw);
    softmax_avg_kernel<<<dim3(1024, Bsz), 512, smem_sm>>>(aw, awh, aw_avg);
    cudaStreamWaitEvent(0, g_ev_vt, 0);
    gemm_av_kernel<<<dim3(8, BH), 256, smem_av>>>(awh, vth, attn);

    // join freq path before the output conv
    cudaStreamWaitEvent(0, g_ev_join, 0);

    // output conv
    conv_mma_kernel<32, 2, 1><<<dim3(256, 4, 4), 256, smem_conv_out>>>(
        attn, out_w, out_b, out, nullptr, nullptr);
}